// round 14
// baseline (speedup 1.0000x reference)
#include <cuda_runtime.h>
#include <cuda_fp16.h>
#include <cstdint>

#define DINL __device__ __forceinline__
#define N_NODES 25000
#define N_EDGES 300000
#define N_GRAPHS 256

// ---------------- helpers ----------------

DINL uint32_t smem_u32(const void* p) {
    uint32_t a;
    asm("{ .reg .u64 t; cvta.to.shared.u64 t, %1; cvt.u32.u64 %0, t; }" : "=r"(a) : "l"(p));
    return a;
}
DINL float sp(float x) {
    return fmaxf(x, 0.f) + __logf(1.f + __expf(-fabsf(x)));
}
DINL void red4(float* a, float x, float y, float z, float w) {
    asm volatile("red.global.add.v4.f32 [%0], {%1, %2, %3, %4};"
                 :: "l"(a), "f"(x), "f"(y), "f"(z), "f"(w) : "memory");
}
DINL uint32_t pkhf(float lo, float hi) {
    uint32_t u;
    asm("cvt.rn.f16x2.f32 %0, %1, %2;" : "=r"(u) : "f"(hi), "f"(lo));
    return u;
}
DINL void ldsm4(uint32_t& r0, uint32_t& r1, uint32_t& r2, uint32_t& r3, uint32_t a) {
    asm volatile("ldmatrix.sync.aligned.m8n8.x4.shared.b16 {%0,%1,%2,%3}, [%4];"
                 : "=r"(r0), "=r"(r1), "=r"(r2), "=r"(r3) : "r"(a));
}
DINL void mma_f16(float* d, const uint32_t* a, const uint32_t* b) {
    asm volatile("mma.sync.aligned.m16n8k16.row.col.f32.f16.f16.f32 "
                 "{%0,%1,%2,%3}, {%4,%5,%6,%7}, {%8,%9}, {%0,%1,%2,%3};"
                 : "+f"(d[0]), "+f"(d[1]), "+f"(d[2]), "+f"(d[3])
                 : "r"(a[0]), "r"(a[1]), "r"(a[2]), "r"(a[3]), "r"(b[0]), "r"(b[1]));
}
// K-major SW128 blocked-atom byte offset (swizzle affects only k-byte bits 4..6)
DINL int imgoff(int r, int k, int nra) {
    int base = ((r >> 3) + (k >> 6) * nra) * 1024 + (r & 7) * 128;
    int kb = ((k & 63) << 1) ^ ((r & 7) << 4);
    return base + kb;
}
// fragment-column -> actual-channel permutation
DINL int chan(int p) {
    int q = p & 15;
    int cl = (q < 8) ? (((q >> 1) << 2) | (q & 1))
                     : ((((q - 8) >> 1) << 2) | 2 | (q & 1));
    return (p & ~15) | cl;
}

// build one edge's A entries at k-pair (k, k+1)
template <int K>
DINL void build_edge(char* As, const float* ws1, const float* eas, int e, int k) {
    float a0 = eas[e * 5 + 0], a1 = eas[e * 5 + 1];
    float a2 = eas[e * 5 + 2], a3 = eas[e * 5 + 3];
    float z0 = fmaf(a0, ws1[k],
               fmaf(a1, ws1[K + k],
               fmaf(a2, ws1[2 * K + k],
               fmaf(a3, ws1[3 * K + k], ws1[4 * K + k]))));
    float z1 = fmaf(a0, ws1[k + 1],
               fmaf(a1, ws1[K + k + 1],
               fmaf(a2, ws1[2 * K + k + 1],
               fmaf(a3, ws1[3 * K + k + 1], ws1[4 * K + k + 1]))));
    *(uint32_t*)(As + imgoff(e, k, 16)) = pkhf(sp(z0), sp(z1));
}

template <int NLD, int NT8>
DINL void mma_step(uint32_t ab0, uint32_t ab1, const uint32_t* bb,
                   uint32_t akadd, uint32_t bkadd, float (*acc)[NT8][4]) {
    uint32_t af0[4], af1[4];
    ldsm4(af0[0], af0[1], af0[2], af0[3], ab0 + akadd);
    ldsm4(af1[0], af1[1], af1[2], af1[3], ab1 + akadd);
    uint32_t bf[NLD][4];
#pragma unroll
    for (int j = 0; j < NLD; j++)
        ldsm4(bf[j][0], bf[j][1], bf[j][2], bf[j][3], bb[j] + bkadd);
#pragma unroll
    for (int j = 0; j < NLD; j++) {
        mma_f16(acc[0][2 * j], af0, bf[j]);
        mma_f16(acc[0][2 * j + 1], af0, bf[j] + 2);
        mma_f16(acc[1][2 * j], af1, bf[j]);
        mma_f16(acc[1][2 * j + 1], af1, bf[j] + 2);
    }
}

// Edge epilogue with dst-segmented in-warp reduction (rows sorted by dst).
// Rows owned by lane-groups of stride 4 (tq = lane>>2); suffix-sum merges rows
// with equal dst, only segment heads issue red4.
template <int N, int PEP, int NT8>
DINL void edge_epi(const float (*acc)[NT8][4], const float* __restrict__ xs,
                   float* __restrict__ outp, const float* biass,
                   const int* ss, const int* ds,
                   int wm, int colb, int tq, int tr) {
#pragma unroll
    for (int mi = 0; mi < 2; mi++) {
#pragma unroll
        for (int hf = 0; hf < 2; hf++) {
            int row = wm * 32 + mi * 16 + hf * 8 + tq;
            int s = ss[row];
            int d = (s >= 0) ? ds[row] : -1;
            float4 m[PEP];
#pragma unroll
            for (int p = 0; p < PEP; p++) {
                int c0 = colb + p * 16 + tr * 4;
                float4 bv = *(const float4*)(biass + c0);
                if (s >= 0) {
                    float4 xv = __ldg((const float4*)(xs + (size_t)s * N + c0));
                    m[p].x = (acc[mi][2 * p][2 * hf] + bv.x) * xv.x;
                    m[p].y = (acc[mi][2 * p][2 * hf + 1] + bv.y) * xv.y;
                    m[p].z = (acc[mi][2 * p + 1][2 * hf] + bv.z) * xv.z;
                    m[p].w = (acc[mi][2 * p + 1][2 * hf + 1] + bv.w) * xv.w;
                } else {
                    m[p] = make_float4(0.f, 0.f, 0.f, 0.f);
                }
            }
            // segmented suffix-sum over tq (8 rows, lane stride 4)
#pragma unroll
            for (int st = 1; st < 8; st <<= 1) {
                int od = __shfl_down_sync(0xFFFFFFFFu, d, st * 4);
                bool take = (tq + st < 8) && (od == d);
#pragma unroll
                for (int p = 0; p < PEP; p++) {
                    float ox = __shfl_down_sync(0xFFFFFFFFu, m[p].x, st * 4);
                    float oy = __shfl_down_sync(0xFFFFFFFFu, m[p].y, st * 4);
                    float oz = __shfl_down_sync(0xFFFFFFFFu, m[p].z, st * 4);
                    float ow = __shfl_down_sync(0xFFFFFFFFu, m[p].w, st * 4);
                    if (take) {
                        m[p].x += ox; m[p].y += oy; m[p].z += oz; m[p].w += ow;
                    }
                }
            }
            int pd = __shfl_up_sync(0xFFFFFFFFu, d, 4);
            bool head = (tq == 0) || (pd != d);
            if (head && d >= 0) {
#pragma unroll
                for (int p = 0; p < PEP; p++) {
                    int c0 = colb + p * 16 + tr * 4;
                    red4(outp + (size_t)d * N + c0, m[p].x, m[p].y, m[p].z, m[p].w);
                }
            }
        }
    }
}

// ---------------- scratch ----------------

__device__ float g_x0[N_NODES * 128];
__device__ float g_xa[N_NODES * 256];
__device__ float g_xb[N_NODES * 256];
__device__ float g_agg[N_NODES * 256];   // invariant: all-zero between runs
__device__ float g_sums[N_GRAPHS * 256];
__device__ float g_cnt[N_GRAPHS];
__device__ __half g_imgE0[128 * 128];
__device__ __half g_imgE[3 * 256 * 256];
__device__ __half g_imgN0[256 * 128];
__device__ __half g_imgN[3 * 256 * 256];
// edge sort (by dst) scratch
__device__ int g_woff[N_NODES];
__device__ int g_ssrc[N_EDGES];
__device__ int g_sdst[N_EDGES];
__device__ float4 g_sea[N_EDGES];

// ---------------- small kernels ----------------

__global__ void zero2_k(float* __restrict__ a, int na, float* __restrict__ b, int nb) {
    int i = blockIdx.x * blockDim.x + threadIdx.x;
    if (i < na) a[i] = 0.f;
    if (i < nb) b[i] = 0.f;
}

__global__ void zeroi_k(int* __restrict__ p, int n) {
    int i = blockIdx.x * blockDim.x + threadIdx.x;
    if (i < n) p[i] = 0;
}

__global__ void embed_k(const int* __restrict__ xa, const float* __restrict__ emb,
                        float* __restrict__ x0) {
    int i = blockIdx.x * blockDim.x + threadIdx.x;
    if (i < N_NODES * 128) {
        int v = i >> 7, c = i & 127;
        x0[i] = (c < 92) ? emb[xa[v] * 92 + c] : 0.f;
    }
}

// counting sort by dst: histogram -> in-place exclusive scan -> scatter
__global__ void hist_k(const int* __restrict__ dst, int* __restrict__ cnt) {
    int i = blockIdx.x * blockDim.x + threadIdx.x;
    if (i < N_EDGES) atomicAdd(&cnt[dst[i]], 1);
}

__global__ void scan_k(int* __restrict__ a) {
    __shared__ int buf[1024];
    __shared__ int basev;
    int tid = threadIdx.x;
    if (tid == 0) basev = 0;
    __syncthreads();
    for (int c = 0; c < N_NODES; c += 1024) {
        int v = (c + tid < N_NODES) ? a[c + tid] : 0;
        buf[tid] = v;
        __syncthreads();
        for (int s = 1; s < 1024; s <<= 1) {
            int t = (tid >= s) ? buf[tid - s] : 0;
            __syncthreads();
            buf[tid] += t;
            __syncthreads();
        }
        int incl = buf[tid];
        int b = basev;
        if (c + tid < N_NODES) a[c + tid] = b + incl - v;
        __syncthreads();
        if (tid == 1023) basev = b + buf[1023];
        __syncthreads();
    }
}

__global__ void scatter_k(const int* __restrict__ src, const int* __restrict__ dst,
                          const float4* __restrict__ ea, int* __restrict__ cur,
                          int* __restrict__ ssrc, int* __restrict__ sdst,
                          float4* __restrict__ sea) {
    int i = blockIdx.x * blockDim.x + threadIdx.x;
    if (i >= N_EDGES) return;
    int d = dst[i];
    int p = atomicAdd(&cur[d], 1);
    ssrc[p] = src[i];
    sdst[p] = d;
    sea[p] = ea[i];
}

DINL void prep_one(const float* w, __half* img, int K, int N, int CRk, int CRn, int i) {
    int p = i / K, k = i - p * K;
    int c = chan(p);
    float v = (k < CRk && c < CRn) ? w[k * CRn + c] : 0.f;
    *(__half*)((char*)img + imgoff(p, k, N >> 3)) = __float2half(v);
}

__global__ void prep_all_k(const float* __restrict__ ew2_0, const float* __restrict__ nw_0,
                           const float* __restrict__ ew2, const float* __restrict__ nw,
                           __half* __restrict__ imgE0, __half* __restrict__ imgN0,
                           __half* __restrict__ imgE, __half* __restrict__ imgN) {
    int i = blockIdx.x * blockDim.x + threadIdx.x;
    if (i < 16384) {
        prep_one(ew2_0, imgE0, 128, 128, 92, 92, i);
    } else if (i < 16384 + 32768) {
        prep_one(nw_0, imgN0, 128, 256, 92, 256, i - 16384);
    } else if (i < 16384 + 32768 + 3 * 65536) {
        int j = i - 16384 - 32768;
        int l = j >> 16;
        prep_one(ew2 + l * 65536, imgE + l * 65536, 256, 256, 256, 256, j & 65535);
    } else if (i < 16384 + 32768 + 6 * 65536) {
        int j = i - 16384 - 32768 - 3 * 65536;
        int l = j >> 16;
        prep_one(nw + l * 65536, imgN + l * 65536, 256, 256, 256, 256, j & 65535);
    }
}

// ---------------- fused HMMA tile kernel (512 threads, persistent, pipelined) ----------------
template <int K, int N, bool EDGE>
__global__ __launch_bounds__(512, 1)
void gemm_tile_k(const float* __restrict__ xs, const float4* __restrict__ sea,
                 const int* __restrict__ ssrc, const int* __restrict__ sdst,
                 const float* __restrict__ w1, const float* __restrict__ b1,
                 const __half* __restrict__ bimg, const float* __restrict__ bias,
                 int CRb, float* __restrict__ outp, float* __restrict__ zbuf,
                 int count, int ntiles) {
    constexpr int A_BYTES = 128 * K * 2;
    constexpr int B_BYTES = N * K * 2;
    constexpr int ASTR = 16 * 1024;
    constexpr int BSTR = (N / 8) * 1024;
    constexpr int KH = K / 2;
    constexpr int STEPS = KH / 16;        // mma steps per k-half
    constexpr int NWP = N / 8;            // cols per warp per pass
    constexpr int NLD = NWP / 16;
    constexpr int NT8 = NWP / 8;
    constexpr int PEP = NWP / 16;
    // edge build geometry (per half)
    constexpr int PAIRS_H = K / 4;
    constexpr int EG_H = 512 / PAIRS_H;
    constexpr int EPT_H = 128 / EG_H;
    constexpr int EPS = EPT_H / STEPS;
    // node build geometry (per half)
    constexpr int KTH = K / 8;
    constexpr int VG_H = 512 / KTH;

    extern __shared__ char smem[];
    char* As = smem;
    char* Bs = smem + A_BYTES;
    float* ws1 = (float*)(Bs + B_BYTES);   // [5][K]
    float* biass = ws1 + 5 * K;            // [N]
    float* eas = biass + N;                // [128][5]
    int* ss = (int*)(eas + 128 * 5);
    int* ds = ss + 128;

    const int tid = threadIdx.x;
    const int lane = tid & 31;
    const int warp = tid >> 5;
    const int wm = warp & 3, wn = warp >> 2;
    const int lr = lane & 7, lg = lane >> 3;
    const int tq = lane >> 2, tr = lane & 3;

    // one-time staging
    if (EDGE) {
        for (int i = tid; i < 5 * K; i += 512) {
            int m = i / K, k = i - m * K;
            ws1[i] = (k < CRb) ? ((m < 4) ? w1[m * CRb + k] : b1[k]) : 0.f;
        }
    }
    for (int i = tid; i < N; i += 512) biass[i] = (i < CRb) ? bias[i] : 0.f;
    {
        const float4* g = (const float4*)bimg;
        float4* s = (float4*)Bs;
        for (int i = tid; i < B_BYTES / 16; i += 512) s[i] = g[i];
    }

    const uint32_t smbA = smem_u32(As);
    const uint32_t smbB = smem_u32(Bs);
    const uint32_t sw = (uint32_t)(lr << 4);
    const int kofA = (lg >> 1) * 8;
    const int kofB = (lg & 1) * 8;
    const uint32_t ab0 = smbA + (uint32_t)((wm * 4 + (lg & 1)) * 1024 + lr * 128);
    const uint32_t ab1 = ab0 + 2 * 1024;

    const int kp = (tid & (PAIRS_H - 1)) * 2;
    const int grp = tid / PAIRS_H;
    const int kq = tid & (KTH - 1);
    const int k4 = kq * 4;
    const int vg = tid / KTH;

    for (int t = blockIdx.x; t < ntiles; t += gridDim.x) {
        __syncthreads();

        const int v0 = t * 128;

        if (EDGE) {
            for (int i = tid; i < 128; i += 512) {
                int eg = t * 128 + i;
                if (eg < count) {
                    ss[i] = ssrc[eg];
                    ds[i] = sdst[eg];
                    float4 v = sea[eg];
                    eas[i * 5 + 0] = v.x; eas[i * 5 + 1] = v.y;
                    eas[i * 5 + 2] = v.z; eas[i * 5 + 3] = v.w;
                } else {
                    ss[i] = -1; ds[i] = 0;
                    eas[i * 5 + 0] = 0.f; eas[i * 5 + 1] = 0.f;
                    eas[i * 5 + 2] = 0.f; eas[i * 5 + 3] = 0.f;
                }
            }
            __syncthreads();
        }

        // ---- build half1 (and prefetch half2 for NODE) ----
        float4 pre[STEPS];
        if (EDGE) {
#pragma unroll
            for (int i = 0; i < EPT_H; i++)
                build_edge<K>(As, ws1, eas, grp + i * EG_H, kp);
        } else {
#pragma unroll
            for (int i = 0; i < STEPS; i++) {
                int gv = v0 + vg + i * VG_H;
                pre[i] = (gv < count)
                    ? __ldg((const float4*)(xs + (size_t)gv * K + k4 + KH))
                    : make_float4(0.f, 0.f, 0.f, 0.f);
            }
#pragma unroll
            for (int i = 0; i < STEPS; i++) {
                int v = vg + i * VG_H;
                int gv = v0 + v;
                float4 av = (gv < count)
                    ? __ldg((const float4*)(xs + (size_t)gv * K + k4))
                    : make_float4(0.f, 0.f, 0.f, 0.f);
                int off = imgoff(v, k4, 16);
                *(uint32_t*)(As + off) = pkhf(av.x, av.y);
                *(uint32_t*)(As + off + 4) = pkhf(av.z, av.w);
            }
        }
        __syncthreads();

        float acc[2][NT8][4];
        uint32_t bb[NLD];

        // ================= pass np = 0 =================
#pragma unroll
        for (int mi = 0; mi < 2; mi++)
#pragma unroll
            for (int ni = 0; ni < NT8; ni++)
#pragma unroll
                for (int q = 0; q < 4; q++) acc[mi][ni][q] = 0.f;
        {
            int batom = (wn * (N / 4)) >> 3;
#pragma unroll
            for (int j = 0; j < NLD; j++)
                bb[j] = smbB + (uint32_t)((batom + j * 2 + (lg >> 1)) * 1024 + lr * 128);
        }
#pragma unroll
        for (int s = 0; s < STEPS; s++) {
            int k0 = s * 16;
            uint32_t blk = (uint32_t)(k0 >> 6);
            uint32_t akadd = blk * ASTR + ((uint32_t)(((k0 & 63) + kofA) << 1) ^ sw);
            uint32_t bkadd = blk * BSTR + ((uint32_t)(((k0 & 63) + kofB) << 1) ^ sw);
            mma_step<NLD, NT8>(ab0, ab1, bb, akadd, bkadd, acc);
            if (EDGE) {
#pragma unroll
                for (int j = 0; j < EPS; j++)
                    build_edge<K>(As, ws1, eas, grp + (s * EPS + j) * EG_H, kp + KH);
            } else {
                int v = vg + s * VG_H;
                int off = imgoff(v, k4 + KH, 16);
                *(uint32_t*)(As + off) = pkhf(pre[s].x, pre[s].y);
                *(uint32_t*)(As + off + 4) = pkhf(pre[s].z, pre[s].w);
            }
        }
        __syncthreads();
#pragma unroll
        for (int s = 0; s < STEPS; s++) {
            int k0 = KH + s * 16;
            uint32_t blk = (uint32_t)(k0 >> 6);
            uint32_t akadd = blk * ASTR + ((uint32_t)(((k0 & 63) + kofA) << 1) ^ sw);
            uint32_t bkadd = blk * BSTR + ((uint32_t)(((k0 & 63) + kofB) << 1) ^ sw);
            mma_step<NLD, NT8>(ab0, ab1, bb, akadd, bkadd, acc);
        }
        // epilogue np = 0
        {
            const int colb = wn * (N / 4);
            if (EDGE) {
                edge_epi<N, PEP, NT8>(acc, xs, outp, biass, ss, ds, wm, colb, tq, tr);
            } else {
#pragma unroll
                for (int mi = 0; mi < 2; mi++)
#pragma unroll
                    for (int hf = 0; hf < 2; hf++) {
                        int row = wm * 32 + mi * 16 + tq + hf * 8;
                        int gv = v0 + row;
                        if (gv >= count) continue;
                        float* yrow = outp + (size_t)gv * 256;
#pragma unroll
                        for (int p = 0; p < PEP; p++) {
                            int c0 = colb + p * 16 + tr * 4;
                            float4 bv = *(const float4*)(biass + c0);
                            float a0 = acc[mi][2 * p][2 * hf], a1 = acc[mi][2 * p][2 * hf + 1];
                            float a2 = acc[mi][2 * p + 1][2 * hf], a3 = acc[mi][2 * p + 1][2 * hf + 1];
                            *(float4*)(yrow + c0) = make_float4(
                                sp(a0 + bv.x), sp(a1 + bv.y), sp(a2 + bv.z), sp(a3 + bv.w));
                        }
                    }
            }
        }

        // ================= pass np = 1 =================
#pragma unroll
        for (int mi = 0; mi < 2; mi++)
#pragma unroll
            for (int ni = 0; ni < NT8; ni++)
#pragma unroll
                for (int q = 0; q < 4; q++) acc[mi][ni][q] = 0.f;
        {
            int batom = (wn * (N / 4) + NWP) >> 3;
#pragma unroll
            for (int j = 0; j < NLD; j++)
                bb[j] = smbB + (uint32_t)((batom + j * 2 + (lg >> 1)) * 1024 + lr * 128);
        }
#pragma unroll
        for (int s = 0; s < 2 * STEPS; s++) {
            int k0 = s * 16;
            uint32_t blk = (uint32_t)(k0 >> 6);
            uint32_t akadd = blk * ASTR + ((uint32_t)(((k0 & 63) + kofA) << 1) ^ sw);
            uint32_t bkadd = blk * BSTR + ((uint32_t)(((k0 & 63) + kofB) << 1) ^ sw);
            mma_step<NLD, NT8>(ab0, ab1, bb, akadd, bkadd, acc);
        }
        // epilogue np = 1
        {
            const int colb = wn * (N / 4) + NWP;
            if (EDGE) {
                edge_epi<N, PEP, NT8>(acc, xs, outp, biass, ss, ds, wm, colb, tq, tr);
            } else {
#pragma unroll
                for (int mi = 0; mi < 2; mi++)
#pragma unroll
                    for (int hf = 0; hf < 2; hf++) {
                        int row = wm * 32 + mi * 16 + tq + hf * 8;
                        int gv = v0 + row;
                        if (gv >= count) continue;
                        float* yrow = outp + (size_t)gv * 256;
#pragma unroll
                        for (int p = 0; p < PEP; p++) {
                            int c0 = colb + p * 16 + tr * 4;
                            float4 bv = *(const float4*)(biass + c0);
                            float a0 = acc[mi][2 * p][2 * hf], a1 = acc[mi][2 * p][2 * hf + 1];
                            float a2 = acc[mi][2 * p + 1][2 * hf], a3 = acc[mi][2 * p + 1][2 * hf + 1];
                            *(float4*)(yrow + c0) = make_float4(
                                sp(a0 + bv.x), sp(a1 + bv.y), sp(a2 + bv.z), sp(a3 + bv.w));
                        }
                    }
            }
        }

        // node: restore agg-is-zero invariant
        if (!EDGE) {
            const float4 z4 = make_float4(0.f, 0.f, 0.f, 0.f);
#pragma unroll
            for (int i = 0; i < STEPS; i++) {
                int gv = v0 + vg + i * VG_H;
                if (gv < count) {
                    *(float4*)(zbuf + (size_t)gv * K + k4) = z4;
                    *(float4*)(zbuf + (size_t)gv * K + k4 + KH) = z4;
                }
            }
        }
    }
}

// ---------------- pooling / readout ----------------

__global__ void pool_k(const float* __restrict__ x, const int* __restrict__ batch,
                       float* __restrict__ sums, float* __restrict__ cnt, int N) {
    __shared__ int bs[32];
    int t = threadIdx.x;
    int v0 = blockIdx.x * 32;
    if (t < 32) bs[t] = (v0 + t < N) ? batch[v0 + t] : -1;
    __syncthreads();
    int cur = bs[0];
    if (cur < 0) return;
    float run = 0.f;
    int rl = 0;
    for (int v = 0; v < 32; v++) {
        int bg = bs[v];
        if (bg < 0) break;
        if (bg != cur) {
            atomicAdd(&sums[cur * 256 + t], run);
            if (t == 0) atomicAdd(&cnt[cur], (float)rl);
            run = 0.f; rl = 0; cur = bg;
        }
        run += x[(size_t)(v0 + v) * 256 + t];
        rl++;
    }
    atomicAdd(&sums[cur * 256 + t], run);
    if (t == 0) atomicAdd(&cnt[cur], (float)rl);
}

__global__ void readout_k(const float* __restrict__ sums, const float* __restrict__ cnt,
                          const float* __restrict__ rw1, const float* __restrict__ rb1,
                          const float* __restrict__ rw2, const float* __restrict__ rb2,
                          const float* __restrict__ rw3, const float* __restrict__ rb3,
                          float* __restrict__ out) {
    __shared__ float gv[256];
    __shared__ float hv[256];
    __shared__ float part[4];
    int g = blockIdx.x, t = threadIdx.x;  // 256 threads
    float cn = fmaxf(cnt[g], 1.f);
    gv[t] = sums[g * 256 + t] / cn;
    __syncthreads();
    float acc = rb1[t];
#pragma unroll 8
    for (int k = 0; k < 256; k++) acc = fmaf(gv[k], rw1[k * 256 + t], acc);
    hv[t] = sp(acc);
    __syncthreads();
    if (t < 128) {
        float a2 = rb2[t];
#pragma unroll 8
        for (int k = 0; k < 256; k++) a2 = fmaf(hv[k], rw2[k * 128 + t], a2);
        float p = sp(a2) * rw3[t];
#pragma unroll
        for (int o = 16; o; o >>= 1) p += __shfl_down_sync(0xFFFFFFFFu, p, o);
        if ((t & 31) == 0) part[t >> 5] = p;
    }
    __syncthreads();
    if (t == 0) out[g] = part[0] + part[1] + part[2] + part[3] + rb3[0];
}

// ---------------- launch ----------------

static constexpr int smem_sz(int K, int N) {
    return 128 * K * 2 + N * K * 2 + (5 * K + N + 128 * 5 + 256) * 4 + 64;
}

extern "C" void kernel_launch(void* const* d_in, const int* in_sizes, int n_in,
                              void* d_out, int out_size) {
    const int* x_atoms = (const int*)d_in[0];
    const int* eidx    = (const int*)d_in[1];
    const float* eattr = (const float*)d_in[2];
    const int* batch   = (const int*)d_in[3];
    const float* emb   = (const float*)d_in[4];
    const float* ew1_0 = (const float*)d_in[5];
    const float* eb1_0 = (const float*)d_in[6];
    const float* ew2_0 = (const float*)d_in[7];
    const float* eb2_0 = (const float*)d_in[8];
    const float* nw_0  = (const float*)d_in[9];
    const float* nb_0  = (const float*)d_in[10];
    const float* ew1   = (const float*)d_in[11];
    const float* eb1   = (const float*)d_in[12];
    const float* ew2   = (const float*)d_in[13];
    const float* eb2   = (const float*)d_in[14];
    const float* nw    = (const float*)d_in[15];
    const float* nb    = (const float*)d_in[16];
    const float* rw1   = (const float*)d_in[17];
    const float* rb1   = (const float*)d_in[18];
    const float* rw2   = (const float*)d_in[19];
    const float* rb2   = (const float*)d_in[20];
    const float* rw3   = (const float*)d_in[21];
    const float* rb3   = (const float*)d_in[22];
    float* out = (float*)d_out;

    const int* src = eidx;
    const int* dst = eidx + N_EDGES;

    float *x0, *xa, *xb, *agg, *sums, *cnt;
    __half *imgE0, *imgE, *imgN0, *imgN;
    int *woff, *ssrc, *sdst;
    float4* sea;
    cudaGetSymbolAddress((void**)&x0, g_x0);
    cudaGetSymbolAddress((void**)&xa, g_xa);
    cudaGetSymbolAddress((void**)&xb, g_xb);
    cudaGetSymbolAddress((void**)&agg, g_agg);
    cudaGetSymbolAddress((void**)&sums, g_sums);
    cudaGetSymbolAddress((void**)&cnt, g_cnt);
    cudaGetSymbolAddress((void**)&imgE0, g_imgE0);
    cudaGetSymbolAddress((void**)&imgE, g_imgE);
    cudaGetSymbolAddress((void**)&imgN0, g_imgN0);
    cudaGetSymbolAddress((void**)&imgN, g_imgN);
    cudaGetSymbolAddress((void**)&woff, g_woff);
    cudaGetSymbolAddress((void**)&ssrc, g_ssrc);
    cudaGetSymbolAddress((void**)&sdst, g_sdst);
    cudaGetSymbolAddress((void**)&sea, g_sea);

    cudaFuncSetAttribute(gemm_tile_k<256, 256, true>,
                         cudaFuncAttributeMaxDynamicSharedMemorySize, smem_sz(256, 256));
    cudaFuncSetAttribute(gemm_tile_k<128, 128, true>,
                         cudaFuncAttributeMaxDynamicSharedMemorySize, smem_sz(128, 128));
    cudaFuncSetAttribute(gemm_tile_k<256, 256, false>,
                         cudaFuncAttributeMaxDynamicSharedMemorySize, smem_sz(256, 256));
    cudaFuncSetAttribute(gemm_tile_k<128, 256, false>,
                         cudaFuncAttributeMaxDynamicSharedMemorySize, smem_sz(128, 256));

    // weight images + node embedding + edge sort (independent prep)
    prep_all_k<<<(16384 + 32768 + 6 * 65536 + 255) / 256, 256>>>(
        ew2_0, nw_0, ew2, nw, imgE0, imgN0, imgE, imgN);
    embed_k<<<(N_NODES * 128 + 255) / 256, 256>>>(x_atoms, emb, x0);

    zeroi_k<<<(N_NODES + 255) / 256, 256>>>(woff, N_NODES);
    hist_k<<<(N_EDGES + 255) / 256, 256>>>(dst, woff);
    scan_k<<<1, 1024>>>(woff);
    scatter_k<<<(N_EDGES + 255) / 256, 256>>>(src, dst, (const float4*)eattr, woff,
                                              ssrc, sdst, sea);

    const int EB = (N_EDGES + 127) / 128;   // 2344
    const int NB = (N_NODES + 127) / 128;   // 196
    const int GRID = 148;

    // layer 0 (92 padded to 128); agg is all-zero by invariant
    gemm_tile_k<128, 128, true><<<GRID, 512, smem_sz(128, 128)>>>(
        x0, sea, ssrc, sdst, ew1_0, eb1_0, imgE0, eb2_0, 92, agg, nullptr, N_EDGES, EB);
    gemm_tile_k<128, 256, false><<<GRID, 512, smem_sz(128, 256)>>>(
        agg, nullptr, nullptr, nullptr, nullptr, nullptr, imgN0, nb_0, 256, xa, agg,
        N_NODES, NB);

    // layers 1..3
    const float* xin = xa;
    float* xout = xb;
    for (int i = 0; i < 3; i++) {
        gemm_tile_k<256, 256, true><<<GRID, 512, smem_sz(256, 256)>>>(
            xin, sea, ssrc, sdst, ew1 + i * 4 * 256, eb1 + i * 256,
            imgE + i * 65536, eb2 + i * 256, 256, agg, nullptr, N_EDGES, EB);
        gemm_tile_k<256, 256, false><<<GRID, 512, smem_sz(256, 256)>>>(
            agg, nullptr, nullptr, nullptr, nullptr, nullptr,
            imgN + i * 65536, nb + i * 256, 256, xout, agg, N_NODES, NB);
        const float* t = xin;
        xin = xout;
        xout = (float*)t;
    }

    // pooling + readout
    zero2_k<<<(N_GRAPHS * 256 + 255) / 256, 256>>>(sums, N_GRAPHS * 256, cnt, N_GRAPHS);
    pool_k<<<(N_NODES + 31) / 32, 256>>>(xin, batch, sums, cnt, N_NODES);
    readout_k<<<N_GRAPHS, 256>>>(sums, cnt, rw1, rb1, rw2, rb2, rw3, rb3, out);
}